// round 1
// baseline (speedup 1.0000x reference)
#include <cuda_runtime.h>
#include <math_constants.h>

// Problem constants
#define Bb 4
#define Ss 4096
#define Dd 1024
#define Nn 128   // head dim for q,k and also L (v/out dim)

// Scratch for projected q,k,v (device globals: allocation-guard safe)
__device__ float g_q[(size_t)Bb * Ss * Nn];
__device__ float g_k[(size_t)Bb * Ss * Nn];
__device__ float g_v[(size_t)Bb * Ss * Nn];

// ---------------------------------------------------------------------------
// QKV projection GEMM: C[16384,128] = X[16384,1024] @ W[128,1024]^T
// BM=128, BN=128(full), BK=16, 256 threads, 8x8 microtile.
// blockIdx.y in {0,1,2} selects (Wq->g_q, Wk->g_k, Wv->g_v).
// ---------------------------------------------------------------------------
__global__ __launch_bounds__(256) void qkv_gemm_kernel(
    const float* __restrict__ X,
    const float* __restrict__ Wq,
    const float* __restrict__ Wk,
    const float* __restrict__ Wv)
{
    __shared__ float As[16][132];   // [k][m], padded
    __shared__ float Bs[16][132];   // [k][n], padded

    const float* W;
    float* Out;
    if (blockIdx.y == 0)      { W = Wq; Out = g_q; }
    else if (blockIdx.y == 1) { W = Wk; Out = g_k; }
    else                      { W = Wv; Out = g_v; }

    const int m0  = blockIdx.x * 128;
    const int tid = threadIdx.x;
    const int tr  = tid >> 4;   // 0..15
    const int tc  = tid & 15;   // 0..15

    float acc[8][8];
#pragma unroll
    for (int i = 0; i < 8; i++)
#pragma unroll
        for (int j = 0; j < 8; j++) acc[i][j] = 0.0f;

    for (int k0 = 0; k0 < Dd; k0 += 16) {
        // Load A tile (128 rows x 16 cols) and B tile (128 rows x 16 cols).
        // 512 float4 each; 2 per thread.
#pragma unroll
        for (int l = 0; l < 2; l++) {
            int idx = tid + l * 256;        // 0..511
            int row = idx >> 2;             // 0..127
            int c4  = (idx & 3) * 4;        // 0,4,8,12

            float4 va = *(const float4*)(X + (size_t)(m0 + row) * Dd + k0 + c4);
            As[c4 + 0][row] = va.x;
            As[c4 + 1][row] = va.y;
            As[c4 + 2][row] = va.z;
            As[c4 + 3][row] = va.w;

            float4 vb = *(const float4*)(W + (size_t)row * Dd + k0 + c4);
            Bs[c4 + 0][row] = vb.x;
            Bs[c4 + 1][row] = vb.y;
            Bs[c4 + 2][row] = vb.z;
            Bs[c4 + 3][row] = vb.w;
        }
        __syncthreads();

#pragma unroll
        for (int k = 0; k < 16; k++) {
            float a[8], b[8];
#pragma unroll
            for (int i = 0; i < 8; i++) a[i] = As[k][tr + 16 * i];
#pragma unroll
            for (int j = 0; j < 8; j++) b[j] = Bs[k][tc + 16 * j];
#pragma unroll
            for (int i = 0; i < 8; i++)
#pragma unroll
                for (int j = 0; j < 8; j++) acc[i][j] = fmaf(a[i], b[j], acc[i][j]);
        }
        __syncthreads();
    }

#pragma unroll
    for (int i = 0; i < 8; i++)
#pragma unroll
        for (int j = 0; j < 8; j++)
            Out[(size_t)(m0 + tr + 16 * i) * Nn + tc + 16 * j] = acc[i][j];
}

// ---------------------------------------------------------------------------
// Flash attention: per (q-tile of 128, batch). BN=64 keys per iteration.
// 256 threads: rg = tid/8 owns q-rows rg*4..rg*4+3 ; c = tid%7 owns
// k-cols {c+8j} and O-cols {c+8j}.
// Smem (dynamic): Qs[128][129] Ks[64][129] Vs[64][129] Ps[128][65]
// ---------------------------------------------------------------------------
#define QS_STRIDE 129
#define KS_STRIDE 129
#define PS_STRIDE 65
#define ATT_SMEM_FLOATS (128 * QS_STRIDE + 64 * KS_STRIDE + 64 * KS_STRIDE + 128 * PS_STRIDE)
#define ATT_SMEM_BYTES (ATT_SMEM_FLOATS * 4)

__global__ __launch_bounds__(256) void attn_kernel(float* __restrict__ out)
{
    extern __shared__ float sm[];
    float* Qs = sm;                                  // [128][129]
    float* Ks = Qs + 128 * QS_STRIDE;                // [64][129]
    float* Vs = Ks + 64 * KS_STRIDE;                 // [64][129]
    float* Ps = Vs + 64 * KS_STRIDE;                 // [128][65]

    const int b   = blockIdx.y;
    const int q0  = blockIdx.x * 128;
    const int tid = threadIdx.x;
    const int rg  = tid >> 3;   // 0..31 -> q rows rg*4 + i
    const int c   = tid & 7;    // 0..7  -> cols c + 8*j

    const float* qbase = g_q + ((size_t)b * Ss + q0) * Nn;
    const float* kbase = g_k + (size_t)b * Ss * Nn;
    const float* vbase = g_v + (size_t)b * Ss * Nn;

    // Load Q tile (prescaled by 1/sqrt(D) = 1/32)
    const float inv_scale = 1.0f / 32.0f;
#pragma unroll
    for (int l = 0; l < 16; l++) {
        int idx = tid + l * 256;       // 0..4095 float4 slots
        int row = idx >> 5;            // 0..127
        int c4  = (idx & 31) * 4;      // 0..124
        float4 v = *(const float4*)(qbase + (size_t)row * Nn + c4);
        Qs[row * QS_STRIDE + c4 + 0] = v.x * inv_scale;
        Qs[row * QS_STRIDE + c4 + 1] = v.y * inv_scale;
        Qs[row * QS_STRIDE + c4 + 2] = v.z * inv_scale;
        Qs[row * QS_STRIDE + c4 + 3] = v.w * inv_scale;
    }

    float m_run[4], l_run[4], o[4][16];
#pragma unroll
    for (int i = 0; i < 4; i++) {
        m_run[i] = -CUDART_INF_F;
        l_run[i] = 0.0f;
#pragma unroll
        for (int j = 0; j < 16; j++) o[i][j] = 0.0f;
    }

    for (int k0 = 0; k0 < Ss; k0 += 64) {
        __syncthreads();   // previous PV reads of Ks/Vs/Ps finished
        // Load K and V tiles: 64x128 each => 2048 float4 each, 8 per thread
#pragma unroll
        for (int l = 0; l < 8; l++) {
            int idx = tid + l * 256;   // 0..2047
            int row = idx >> 5;        // 0..63
            int c4  = (idx & 31) * 4;
            float4 kv = *(const float4*)(kbase + (size_t)(k0 + row) * Nn + c4);
            Ks[row * KS_STRIDE + c4 + 0] = kv.x;
            Ks[row * KS_STRIDE + c4 + 1] = kv.y;
            Ks[row * KS_STRIDE + c4 + 2] = kv.z;
            Ks[row * KS_STRIDE + c4 + 3] = kv.w;
            float4 vv = *(const float4*)(vbase + (size_t)(k0 + row) * Nn + c4);
            Vs[row * KS_STRIDE + c4 + 0] = vv.x;
            Vs[row * KS_STRIDE + c4 + 1] = vv.y;
            Vs[row * KS_STRIDE + c4 + 2] = vv.z;
            Vs[row * KS_STRIDE + c4 + 3] = vv.w;
        }
        __syncthreads();

        // S = Q K^T  (4x8 per thread)
        float s[4][8];
#pragma unroll
        for (int i = 0; i < 4; i++)
#pragma unroll
            for (int j = 0; j < 8; j++) s[i][j] = 0.0f;

#pragma unroll 4
        for (int d = 0; d < 128; d++) {
            float qv[4];
#pragma unroll
            for (int i = 0; i < 4; i++) qv[i] = Qs[(rg * 4 + i) * QS_STRIDE + d];
            float kv[8];
#pragma unroll
            for (int j = 0; j < 8; j++) kv[j] = Ks[(c + 8 * j) * KS_STRIDE + d];
#pragma unroll
            for (int i = 0; i < 4; i++)
#pragma unroll
                for (int j = 0; j < 8; j++) s[i][j] = fmaf(qv[i], kv[j], s[i][j]);
        }

        // Online softmax per q-row (reduce across the 8 lanes sharing rg)
#pragma unroll
        for (int i = 0; i < 4; i++) {
            float mx = s[i][0];
#pragma unroll
            for (int j = 1; j < 8; j++) mx = fmaxf(mx, s[i][j]);
#pragma unroll
            for (int off = 1; off < 8; off <<= 1)
                mx = fmaxf(mx, __shfl_xor_sync(0xffffffffu, mx, off));
            float mnew = fmaxf(m_run[i], mx);
            float corr = __expf(m_run[i] - mnew);
            float rs = 0.0f;
#pragma unroll
            for (int j = 0; j < 8; j++) {
                s[i][j] = __expf(s[i][j] - mnew);
                rs += s[i][j];
            }
#pragma unroll
            for (int off = 1; off < 8; off <<= 1)
                rs += __shfl_xor_sync(0xffffffffu, rs, off);
            l_run[i] = l_run[i] * corr + rs;
            m_run[i] = mnew;
#pragma unroll
            for (int j = 0; j < 16; j++) o[i][j] *= corr;
        }

        // Write P to smem
#pragma unroll
        for (int i = 0; i < 4; i++)
#pragma unroll
            for (int j = 0; j < 8; j++)
                Ps[(rg * 4 + i) * PS_STRIDE + (c + 8 * j)] = s[i][j];
        __syncthreads();

        // O += P @ V
#pragma unroll 2
        for (int k = 0; k < 64; k++) {
            float pv[4];
#pragma unroll
            for (int i = 0; i < 4; i++) pv[i] = Ps[(rg * 4 + i) * PS_STRIDE + k];
            float vv[16];
#pragma unroll
            for (int j = 0; j < 16; j++) vv[j] = Vs[k * KS_STRIDE + c + 8 * j];
#pragma unroll
            for (int i = 0; i < 4; i++)
#pragma unroll
                for (int j = 0; j < 16; j++) o[i][j] = fmaf(pv[i], vv[j], o[i][j]);
        }
    }

    // Normalize and store
    float* obase = out + ((size_t)b * Ss + q0) * Nn;
#pragma unroll
    for (int i = 0; i < 4; i++) {
        float inv = 1.0f / l_run[i];
#pragma unroll
        for (int j = 0; j < 16; j++)
            obase[(size_t)(rg * 4 + i) * Nn + c + 8 * j] = o[i][j] * inv;
    }
}

// ---------------------------------------------------------------------------
// Launch
// ---------------------------------------------------------------------------
extern "C" void kernel_launch(void* const* d_in, const int* in_sizes, int n_in,
                              void* d_out, int out_size)
{
    const float* x  = (const float*)d_in[0];
    const float* Wq = (const float*)d_in[1];
    const float* Wk = (const float*)d_in[2];
    const float* Wv = (const float*)d_in[3];
    float* out = (float*)d_out;

    (void)in_sizes; (void)n_in; (void)out_size;

    cudaFuncSetAttribute(attn_kernel,
                         cudaFuncAttributeMaxDynamicSharedMemorySize,
                         ATT_SMEM_BYTES);

    // QKV projections: grid (M/128, 3 weights)
    qkv_gemm_kernel<<<dim3(Ss * Bb / 128, 3), 256>>>(x, Wq, Wk, Wv);

    // Attention: grid (S/128, B), one wave of 128 CTAs
    attn_kernel<<<dim3(Ss / 128, Bb), 256, ATT_SMEM_BYTES>>>(out);
}

// round 3
// speedup vs baseline: 3.0883x; 3.0883x over previous
#include <cuda_runtime.h>
#include <cstdint>
#include <math_constants.h>

// Problem constants
#define Bb 4
#define Ss 4096
#define Dd 1024
#define Nn 128   // head dim for q,k and also L (v/out dim)

// Scratch for projected q,k,v (device globals: allocation-guard safe)
__device__ float g_q[(size_t)Bb * Ss * Nn];
__device__ float g_k[(size_t)Bb * Ss * Nn];
__device__ float g_v[(size_t)Bb * Ss * Nn];

// ---------------------------------------------------------------------------
// Helpers
// ---------------------------------------------------------------------------
__device__ __forceinline__ float f2tf32(float x) {
    uint32_t r;
    asm("cvt.rna.tf32.f32 %0, %1;" : "=r"(r) : "f"(x));
    return __uint_as_float(r);
}

__device__ __forceinline__ void mma_tf32(float* c,
                                         uint32_t a0, uint32_t a1, uint32_t a2, uint32_t a3,
                                         uint32_t b0, uint32_t b1) {
    asm volatile(
        "mma.sync.aligned.m16n8k8.row.col.f32.tf32.tf32.f32 "
        "{%0,%1,%2,%3}, {%4,%5,%6,%7}, {%8,%9}, {%0,%1,%2,%3};"
        : "+f"(c[0]), "+f"(c[1]), "+f"(c[2]), "+f"(c[3])
        : "r"(a0), "r"(a1), "r"(a2), "r"(a3), "r"(b0), "r"(b1));
}

__device__ __forceinline__ uint32_t fbits(float x) { return __float_as_uint(x); }

// ---------------------------------------------------------------------------
// QKV projection GEMM (tf32 tensor cores):
// C[16384,128] = X[16384,1024] @ W[128,1024]^T
// BM=128, BN=128, BK=32, 256 threads (8 warps), warp w owns rows 16w.
// Per warp: 1 m-tile (m16) x 16 n-tiles (n8), k in steps of 8.
// blockIdx.y in {0,1,2} selects (Wq->g_q, Wk->g_k, Wv->g_v).
// ---------------------------------------------------------------------------
#define GS 36   // smem row stride (floats) for X/W tiles (k-contig)

__global__ __launch_bounds__(256, 2) void qkv_gemm_kernel(
    const float* __restrict__ X,
    const float* __restrict__ Wq,
    const float* __restrict__ Wk,
    const float* __restrict__ Wv)
{
    __shared__ float Xs[128 * GS];
    __shared__ float Ws[128 * GS];

    const float* W;
    float* Out;
    if (blockIdx.y == 0)      { W = Wq; Out = g_q; }
    else if (blockIdx.y == 1) { W = Wk; Out = g_k; }
    else                      { W = Wv; Out = g_v; }

    const int m0   = blockIdx.x * 128;
    const int tid  = threadIdx.x;
    const int w    = tid >> 5;
    const int lane = tid & 31;
    const int g    = lane >> 2;   // 0..7
    const int t    = lane & 3;    // 0..3

    float acc[16][4];
#pragma unroll
    for (int nt = 0; nt < 16; nt++)
#pragma unroll
        for (int i = 0; i < 4; i++) acc[nt][i] = 0.0f;

    for (int k0 = 0; k0 < Dd; k0 += 32) {
        // Fill Xs/Ws tiles (128 rows x 32 k each), converted to tf32
#pragma unroll
        for (int l = 0; l < 4; l++) {
            int idx = tid + l * 256;          // 0..1023
            int row = idx >> 3;               // 0..127
            int c4  = (idx & 7) * 4;          // 0..28

            float4 vx = *(const float4*)(X + (size_t)(m0 + row) * Dd + k0 + c4);
            float4 cx = make_float4(f2tf32(vx.x), f2tf32(vx.y), f2tf32(vx.z), f2tf32(vx.w));
            *(float4*)&Xs[row * GS + c4] = cx;

            float4 vw = *(const float4*)(W + (size_t)row * Dd + k0 + c4);
            float4 cw = make_float4(f2tf32(vw.x), f2tf32(vw.y), f2tf32(vw.z), f2tf32(vw.w));
            *(float4*)&Ws[row * GS + c4] = cw;
        }
        __syncthreads();

#pragma unroll
        for (int s = 0; s < 4; s++) {
            const int kc = 8 * s + t;
            uint32_t a0 = fbits(Xs[(16 * w + g) * GS + kc]);
            uint32_t a1 = fbits(Xs[(16 * w + g + 8) * GS + kc]);
            uint32_t a2 = fbits(Xs[(16 * w + g) * GS + kc + 4]);
            uint32_t a3 = fbits(Xs[(16 * w + g + 8) * GS + kc + 4]);
#pragma unroll
            for (int nt = 0; nt < 16; nt++) {
                uint32_t b0 = fbits(Ws[(8 * nt + g) * GS + kc]);
                uint32_t b1 = fbits(Ws[(8 * nt + g) * GS + kc + 4]);
                mma_tf32(acc[nt], a0, a1, a2, a3, b0, b1);
            }
        }
        __syncthreads();
    }

    const size_t row0 = (size_t)(m0 + 16 * w + g);
#pragma unroll
    for (int nt = 0; nt < 16; nt++) {
        *(float2*)&Out[row0 * Nn + 8 * nt + 2 * t]       = make_float2(acc[nt][0], acc[nt][1]);
        *(float2*)&Out[(row0 + 8) * Nn + 8 * nt + 2 * t] = make_float2(acc[nt][2], acc[nt][3]);
    }
}

// ---------------------------------------------------------------------------
// Flash attention with tf32 mma.sync.
// Per CTA: 128 q-rows x batch; 64 keys per iteration; 256 threads / 8 warps.
// Warp w owns q-rows [16w, 16w+16).
// QK: S(16x64) per warp = 8 n-tiles x 16 k-steps.
// PV: O(16x128) per warp = 16 n-tiles x 8 k-steps over keys.
// Smem: Qs[128][136] Ks[64][136] Vs[64][136] (tf32), Ps[128][68] (tf32 probs)
// Stride 136 = 8 mod 32 -> PV b-fragment loads are conflict-free.
// ---------------------------------------------------------------------------
#define QK_S 136
#define PS_S 68
#define ATT_SMEM_FLOATS (128 * QK_S + 64 * QK_S + 64 * QK_S + 128 * PS_S)
#define ATT_SMEM_BYTES  (ATT_SMEM_FLOATS * 4)

__global__ __launch_bounds__(256, 1) void attn_kernel(float* __restrict__ out)
{
    extern __shared__ float sm[];
    float* Qs = sm;                          // [128][136]
    float* Ks = Qs + 128 * QK_S;             // [64][136]
    float* Vs = Ks + 64 * QK_S;              // [64][136]
    float* Ps = Vs + 64 * QK_S;              // [128][68]

    const int b    = blockIdx.y;
    const int q0   = blockIdx.x * 128;
    const int tid  = threadIdx.x;
    const int w    = tid >> 5;
    const int lane = tid & 31;
    const int g    = lane >> 2;   // 0..7
    const int t    = lane & 3;    // 0..3

    const float* qbase = g_q + ((size_t)b * Ss + q0) * Nn;
    const float* kbase = g_k + (size_t)b * Ss * Nn;
    const float* vbase = g_v + (size_t)b * Ss * Nn;

    // Load Q tile, prescaled by 1/sqrt(D)=1/32, converted to tf32
    const float inv_scale = 1.0f / 32.0f;
#pragma unroll
    for (int l = 0; l < 16; l++) {
        int idx = tid + l * 256;     // 0..4095
        int row = idx >> 5;          // 0..127
        int c4  = (idx & 31) * 4;    // 0..124
        float4 v = *(const float4*)(qbase + (size_t)row * Nn + c4);
        float4 c = make_float4(f2tf32(v.x * inv_scale), f2tf32(v.y * inv_scale),
                               f2tf32(v.z * inv_scale), f2tf32(v.w * inv_scale));
        *(float4*)&Qs[row * QK_S + c4] = c;
    }

    // Online softmax state: this thread covers rows (16w+g) [idx 0] and (16w+g+8) [idx 1]
    float m_run[2] = {-CUDART_INF_F, -CUDART_INF_F};
    float l_run[2] = {0.0f, 0.0f};
    float o[16][4];
#pragma unroll
    for (int nt = 0; nt < 16; nt++)
#pragma unroll
        for (int i = 0; i < 4; i++) o[nt][i] = 0.0f;

    for (int k0 = 0; k0 < Ss; k0 += 64) {
        __syncthreads();   // prior iteration done reading Ks/Vs

        // Fill K and V tiles (64x128 each), tf32
#pragma unroll
        for (int l = 0; l < 8; l++) {
            int idx = tid + l * 256;    // 0..2047
            int row = idx >> 5;         // 0..63
            int c4  = (idx & 31) * 4;
            float4 kv = *(const float4*)(kbase + (size_t)(k0 + row) * Nn + c4);
            *(float4*)&Ks[row * QK_S + c4] =
                make_float4(f2tf32(kv.x), f2tf32(kv.y), f2tf32(kv.z), f2tf32(kv.w));
            float4 vv = *(const float4*)(vbase + (size_t)(k0 + row) * Nn + c4);
            *(float4*)&Vs[row * QK_S + c4] =
                make_float4(f2tf32(vv.x), f2tf32(vv.y), f2tf32(vv.z), f2tf32(vv.w));
        }
        __syncthreads();

        // ---- S = Q K^T : 8 n-tiles (8 keys each) x 16 k-steps ----
        float sc[8][4];
#pragma unroll
        for (int nt = 0; nt < 8; nt++)
#pragma unroll
            for (int i = 0; i < 4; i++) sc[nt][i] = 0.0f;

#pragma unroll
        for (int s = 0; s < 16; s++) {
            const int kc = 8 * s + t;
            uint32_t a0 = fbits(Qs[(16 * w + g) * QK_S + kc]);
            uint32_t a1 = fbits(Qs[(16 * w + g + 8) * QK_S + kc]);
            uint32_t a2 = fbits(Qs[(16 * w + g) * QK_S + kc + 4]);
            uint32_t a3 = fbits(Qs[(16 * w + g + 8) * QK_S + kc + 4]);
#pragma unroll
            for (int nt = 0; nt < 8; nt++) {
                uint32_t b0 = fbits(Ks[(8 * nt + g) * QK_S + kc]);
                uint32_t b1 = fbits(Ks[(8 * nt + g) * QK_S + kc + 4]);
                mma_tf32(sc[nt], a0, a1, a2, a3, b0, b1);
            }
        }

        // ---- Online softmax (rows fully owned per warp; 4-lane groups share a row) ----
        // Row 0: elems sc[nt][0], sc[nt][1]; Row 1: sc[nt][2], sc[nt][3]
        {
            float mx0 = -CUDART_INF_F, mx1 = -CUDART_INF_F;
#pragma unroll
            for (int nt = 0; nt < 8; nt++) {
                mx0 = fmaxf(mx0, fmaxf(sc[nt][0], sc[nt][1]));
                mx1 = fmaxf(mx1, fmaxf(sc[nt][2], sc[nt][3]));
            }
#pragma unroll
            for (int off = 1; off < 4; off <<= 1) {
                mx0 = fmaxf(mx0, __shfl_xor_sync(0xffffffffu, mx0, off));
                mx1 = fmaxf(mx1, __shfl_xor_sync(0xffffffffu, mx1, off));
            }
            float mn0 = fmaxf(m_run[0], mx0);
            float mn1 = fmaxf(m_run[1], mx1);
            float corr0 = __expf(m_run[0] - mn0);
            float corr1 = __expf(m_run[1] - mn1);

            float s0 = 0.0f, s1 = 0.0f;
#pragma unroll
            for (int nt = 0; nt < 8; nt++) {
                sc[nt][0] = __expf(sc[nt][0] - mn0);
                sc[nt][1] = __expf(sc[nt][1] - mn0);
                sc[nt][2] = __expf(sc[nt][2] - mn1);
                sc[nt][3] = __expf(sc[nt][3] - mn1);
                s0 += sc[nt][0] + sc[nt][1];
                s1 += sc[nt][2] + sc[nt][3];
            }
#pragma unroll
            for (int off = 1; off < 4; off <<= 1) {
                s0 += __shfl_xor_sync(0xffffffffu, s0, off);
                s1 += __shfl_xor_sync(0xffffffffu, s1, off);
            }
            l_run[0] = l_run[0] * corr0 + s0;
            l_run[1] = l_run[1] * corr1 + s1;
            m_run[0] = mn0;
            m_run[1] = mn1;
#pragma unroll
            for (int nt = 0; nt < 16; nt++) {
                o[nt][0] *= corr0;
                o[nt][1] *= corr0;
                o[nt][2] *= corr1;
                o[nt][3] *= corr1;
            }
        }

        // ---- Write P (tf32) to smem; probs in [0,1], rna conversion ----
#pragma unroll
        for (int nt = 0; nt < 8; nt++) {
            *(float2*)&Ps[(16 * w + g) * PS_S + 8 * nt + 2 * t] =
                make_float2(f2tf32(sc[nt][0]), f2tf32(sc[nt][1]));
            *(float2*)&Ps[(16 * w + g + 8) * PS_S + 8 * nt + 2 * t] =
                make_float2(f2tf32(sc[nt][2]), f2tf32(sc[nt][3]));
        }
        __syncwarp();   // P rows of warp w are read only by warp w

        // ---- O += P @ V : 16 n-tiles (d cols) x 8 k-steps (keys) ----
#pragma unroll
        for (int s = 0; s < 8; s++) {
            const int kc = 8 * s + t;
            uint32_t a0 = fbits(Ps[(16 * w + g) * PS_S + kc]);
            uint32_t a1 = fbits(Ps[(16 * w + g + 8) * PS_S + kc]);
            uint32_t a2 = fbits(Ps[(16 * w + g) * PS_S + kc + 4]);
            uint32_t a3 = fbits(Ps[(16 * w + g + 8) * PS_S + kc + 4]);
#pragma unroll
            for (int nt = 0; nt < 16; nt++) {
                uint32_t b0 = fbits(Vs[(8 * s + t) * QK_S + 8 * nt + g]);
                uint32_t b1 = fbits(Vs[(8 * s + t + 4) * QK_S + 8 * nt + g]);
                mma_tf32(o[nt], a0, a1, a2, a3, b0, b1);
            }
        }
    }

    // ---- Normalize and store ----
    const float inv0 = 1.0f / l_run[0];
    const float inv1 = 1.0f / l_run[1];
    float* obase = out + ((size_t)b * Ss + q0 + 16 * w + g) * Nn;
#pragma unroll
    for (int nt = 0; nt < 16; nt++) {
        *(float2*)&obase[8 * nt + 2 * t] =
            make_float2(o[nt][0] * inv0, o[nt][1] * inv0);
        *(float2*)&obase[8 * (size_t)Nn + 8 * nt + 2 * t] =
            make_float2(o[nt][2] * inv1, o[nt][3] * inv1);
    }
}

// ---------------------------------------------------------------------------
// Launch
// ---------------------------------------------------------------------------
extern "C" void kernel_launch(void* const* d_in, const int* in_sizes, int n_in,
                              void* d_out, int out_size)
{
    const float* x  = (const float*)d_in[0];
    const float* Wq = (const float*)d_in[1];
    const float* Wk = (const float*)d_in[2];
    const float* Wv = (const float*)d_in[3];
    float* out = (float*)d_out;

    (void)in_sizes; (void)n_in; (void)out_size;

    cudaFuncSetAttribute(attn_kernel,
                         cudaFuncAttributeMaxDynamicSharedMemorySize,
                         ATT_SMEM_BYTES);

    qkv_gemm_kernel<<<dim3(Ss * Bb / 128, 3), 256>>>(x, Wq, Wk, Wv);
    attn_kernel<<<dim3(Ss / 128, Bb), 256, ATT_SMEM_BYTES>>>(out);
}

// round 4
// speedup vs baseline: 3.6240x; 1.1735x over previous
#include <cuda_runtime.h>
#include <cstdint>
#include <math_constants.h>

// Problem constants
#define Bb 4
#define Ss 4096
#define Dd 1024
#define Nn 128   // head dim for q,k and also L (v/out dim)

// Scratch for projected q,k,v (device globals: allocation-guard safe)
__device__ float g_q[(size_t)Bb * Ss * Nn];
__device__ float g_k[(size_t)Bb * Ss * Nn];
__device__ float g_v[(size_t)Bb * Ss * Nn];

// ---------------------------------------------------------------------------
// Helpers
// ---------------------------------------------------------------------------
__device__ __forceinline__ float f2tf32(float x) {
    uint32_t r;
    asm("cvt.rna.tf32.f32 %0, %1;" : "=r"(r) : "f"(x));
    return __uint_as_float(r);
}

__device__ __forceinline__ void mma_tf32(float* c,
                                         uint32_t a0, uint32_t a1, uint32_t a2, uint32_t a3,
                                         uint32_t b0, uint32_t b1) {
    asm volatile(
        "mma.sync.aligned.m16n8k8.row.col.f32.tf32.tf32.f32 "
        "{%0,%1,%2,%3}, {%4,%5,%6,%7}, {%8,%9}, {%0,%1,%2,%3};"
        : "+f"(c[0]), "+f"(c[1]), "+f"(c[2]), "+f"(c[3])
        : "r"(a0), "r"(a1), "r"(a2), "r"(a3), "r"(b0), "r"(b1));
}

__device__ __forceinline__ uint32_t fbits(float x) { return __float_as_uint(x); }

// ---------------------------------------------------------------------------
// QKV projection GEMM (tf32 tensor cores):
// C[16384,128] = X[16384,1024] @ W[128,1024]^T
// BM=128, BN=128, BK=32, 256 threads (8 warps), warp w owns rows 16w.
// ---------------------------------------------------------------------------
#define GS 36   // smem row stride (floats), 36 mod 32 = 4 -> conflict-free frags

__global__ __launch_bounds__(256, 2) void qkv_gemm_kernel(
    const float* __restrict__ X,
    const float* __restrict__ Wq,
    const float* __restrict__ Wk,
    const float* __restrict__ Wv)
{
    __shared__ float Xs[128 * GS];
    __shared__ float Ws[128 * GS];

    const float* W;
    float* Out;
    if (blockIdx.y == 0)      { W = Wq; Out = g_q; }
    else if (blockIdx.y == 1) { W = Wk; Out = g_k; }
    else                      { W = Wv; Out = g_v; }

    const int m0   = blockIdx.x * 128;
    const int tid  = threadIdx.x;
    const int w    = tid >> 5;
    const int lane = tid & 31;
    const int g    = lane >> 2;   // 0..7
    const int t    = lane & 3;    // 0..3

    float acc[16][4];
#pragma unroll
    for (int nt = 0; nt < 16; nt++)
#pragma unroll
        for (int i = 0; i < 4; i++) acc[nt][i] = 0.0f;

    for (int k0 = 0; k0 < Dd; k0 += 32) {
#pragma unroll
        for (int l = 0; l < 4; l++) {
            int idx = tid + l * 256;          // 0..1023
            int row = idx >> 3;               // 0..127
            int c4  = (idx & 7) * 4;          // 0..28

            float4 vx = *(const float4*)(X + (size_t)(m0 + row) * Dd + k0 + c4);
            float4 cx = make_float4(f2tf32(vx.x), f2tf32(vx.y), f2tf32(vx.z), f2tf32(vx.w));
            *(float4*)&Xs[row * GS + c4] = cx;

            float4 vw = *(const float4*)(W + (size_t)row * Dd + k0 + c4);
            float4 cw = make_float4(f2tf32(vw.x), f2tf32(vw.y), f2tf32(vw.z), f2tf32(vw.w));
            *(float4*)&Ws[row * GS + c4] = cw;
        }
        __syncthreads();

#pragma unroll
        for (int s = 0; s < 4; s++) {
            const int kc = 8 * s + t;
            uint32_t a0 = fbits(Xs[(16 * w + g) * GS + kc]);
            uint32_t a1 = fbits(Xs[(16 * w + g + 8) * GS + kc]);
            uint32_t a2 = fbits(Xs[(16 * w + g) * GS + kc + 4]);
            uint32_t a3 = fbits(Xs[(16 * w + g + 8) * GS + kc + 4]);
#pragma unroll
            for (int nt = 0; nt < 16; nt++) {
                uint32_t b0 = fbits(Ws[(8 * nt + g) * GS + kc]);
                uint32_t b1 = fbits(Ws[(8 * nt + g) * GS + kc + 4]);
                mma_tf32(acc[nt], a0, a1, a2, a3, b0, b1);
            }
        }
        __syncthreads();
    }

    const size_t row0 = (size_t)(m0 + 16 * w + g);
#pragma unroll
    for (int nt = 0; nt < 16; nt++) {
        *(float2*)&Out[row0 * Nn + 8 * nt + 2 * t]       = make_float2(acc[nt][0], acc[nt][1]);
        *(float2*)&Out[(row0 + 8) * Nn + 8 * nt + 2 * t] = make_float2(acc[nt][2], acc[nt][3]);
    }
}

// ---------------------------------------------------------------------------
// Flash attention, tf32 mma.sync, Q fragments register-resident.
// 128 q-rows per CTA, 64 keys/iter, 8 warps; warp w owns q-rows [16w,16w+16).
// Ks stride 132 (== 4 mod 32): QK B-frag bank = 4g+t  -> conflict-free.
// Vs stride 136 (== 8 mod 32): PV B-frag bank = 8(t+nt)+g -> conflict-free.
// Ps stride 68  (== 4 mod 32): PV A-frag bank = 4g+t  -> conflict-free.
// Smem: Ks[64][132] Vs[64][136] Ps[128][68]  = ~101 KB
// ---------------------------------------------------------------------------
#define KS_S 132
#define VS_S 136
#define PS_S 68
#define ATT_SMEM_FLOATS (64 * KS_S + 64 * VS_S + 128 * PS_S)
#define ATT_SMEM_BYTES  (ATT_SMEM_FLOATS * 4)

__global__ __launch_bounds__(256, 1) void attn_kernel(float* __restrict__ out)
{
    extern __shared__ float sm[];
    float* Ks = sm;                          // [64][132]
    float* Vs = Ks + 64 * KS_S;              // [64][136]
    float* Ps = Vs + 64 * VS_S;              // [128][68]

    const int b    = blockIdx.y;
    const int q0   = blockIdx.x * 128;
    const int tid  = threadIdx.x;
    const int w    = tid >> 5;
    const int lane = tid & 31;
    const int g    = lane >> 2;   // 0..7
    const int t    = lane & 3;    // 0..3

    const float* qbase = g_q + ((size_t)b * Ss + q0) * Nn;
    const float* kbase = g_k + (size_t)b * Ss * Nn;
    const float* vbase = g_v + (size_t)b * Ss * Nn;

    // ---- Stage Q through Ks/Vs, then hoist fragments into registers ----
    const float inv_scale = 1.0f / 32.0f;
#pragma unroll
    for (int l = 0; l < 16; l++) {
        int idx = tid + l * 256;     // 0..4095 float4 slots
        int row = idx >> 5;          // 0..127
        int c4  = (idx & 31) * 4;    // 0..124
        float4 v = *(const float4*)(qbase + (size_t)row * Nn + c4);
        float4 c = make_float4(f2tf32(v.x * inv_scale), f2tf32(v.y * inv_scale),
                               f2tf32(v.z * inv_scale), f2tf32(v.w * inv_scale));
        float* dst = (row < 64) ? &Ks[row * KS_S + c4] : &Vs[(row - 64) * VS_S + c4];
        *(float4*)dst = c;
    }
    __syncthreads();

    uint32_t qa[16][4];
    {
        const float* r0 = (w < 4) ? &Ks[(16 * w + g) * KS_S] : &Vs[(16 * w + g - 64) * VS_S];
        const float* r1 = (w < 4) ? &Ks[(16 * w + g + 8) * KS_S] : &Vs[(16 * w + g - 56) * VS_S];
#pragma unroll
        for (int s = 0; s < 16; s++) {
            const int kc = 8 * s + t;
            qa[s][0] = fbits(r0[kc]);
            qa[s][1] = fbits(r1[kc]);
            qa[s][2] = fbits(r0[kc + 4]);
            qa[s][3] = fbits(r1[kc + 4]);
        }
    }
    __syncthreads();

    // Online softmax state: rows (16w+g) [idx 0] and (16w+g+8) [idx 1]
    float m_run[2] = {-CUDART_INF_F, -CUDART_INF_F};
    float l_run[2] = {0.0f, 0.0f};
    float o[16][4];
#pragma unroll
    for (int nt = 0; nt < 16; nt++)
#pragma unroll
        for (int i = 0; i < 4; i++) o[nt][i] = 0.0f;

    for (int k0 = 0; k0 < Ss; k0 += 64) {
        // Fill K and V tiles (64x128 each), tf32
#pragma unroll
        for (int l = 0; l < 8; l++) {
            int idx = tid + l * 256;    // 0..2047
            int row = idx >> 5;         // 0..63
            int c4  = (idx & 31) * 4;
            float4 kv = *(const float4*)(kbase + (size_t)(k0 + row) * Nn + c4);
            *(float4*)&Ks[row * KS_S + c4] =
                make_float4(f2tf32(kv.x), f2tf32(kv.y), f2tf32(kv.z), f2tf32(kv.w));
            float4 vv = *(const float4*)(vbase + (size_t)(k0 + row) * Nn + c4);
            *(float4*)&Vs[row * VS_S + c4] =
                make_float4(f2tf32(vv.x), f2tf32(vv.y), f2tf32(vv.z), f2tf32(vv.w));
        }
        __syncthreads();

        // ---- S = Q K^T : 8 n-tiles x 16 k-steps, A from registers ----
        float sc[8][4];
#pragma unroll
        for (int nt = 0; nt < 8; nt++)
#pragma unroll
            for (int i = 0; i < 4; i++) sc[nt][i] = 0.0f;

#pragma unroll
        for (int s = 0; s < 16; s++) {
            const int kc = 8 * s + t;
#pragma unroll
            for (int nt = 0; nt < 8; nt++) {
                uint32_t b0 = fbits(Ks[(8 * nt + g) * KS_S + kc]);
                uint32_t b1 = fbits(Ks[(8 * nt + g) * KS_S + kc + 4]);
                mma_tf32(sc[nt], qa[s][0], qa[s][1], qa[s][2], qa[s][3], b0, b1);
            }
        }

        // ---- Online softmax ----
        {
            float mx0 = -CUDART_INF_F, mx1 = -CUDART_INF_F;
#pragma unroll
            for (int nt = 0; nt < 8; nt++) {
                mx0 = fmaxf(mx0, fmaxf(sc[nt][0], sc[nt][1]));
                mx1 = fmaxf(mx1, fmaxf(sc[nt][2], sc[nt][3]));
            }
#pragma unroll
            for (int off = 1; off < 4; off <<= 1) {
                mx0 = fmaxf(mx0, __shfl_xor_sync(0xffffffffu, mx0, off));
                mx1 = fmaxf(mx1, __shfl_xor_sync(0xffffffffu, mx1, off));
            }
            float mn0 = fmaxf(m_run[0], mx0);
            float mn1 = fmaxf(m_run[1], mx1);
            float corr0 = __expf(m_run[0] - mn0);
            float corr1 = __expf(m_run[1] - mn1);

            float s0 = 0.0f, s1 = 0.0f;
#pragma unroll
            for (int nt = 0; nt < 8; nt++) {
                sc[nt][0] = __expf(sc[nt][0] - mn0);
                sc[nt][1] = __expf(sc[nt][1] - mn0);
                sc[nt][2] = __expf(sc[nt][2] - mn1);
                sc[nt][3] = __expf(sc[nt][3] - mn1);
                s0 += sc[nt][0] + sc[nt][1];
                s1 += sc[nt][2] + sc[nt][3];
            }
#pragma unroll
            for (int off = 1; off < 4; off <<= 1) {
                s0 += __shfl_xor_sync(0xffffffffu, s0, off);
                s1 += __shfl_xor_sync(0xffffffffu, s1, off);
            }
            l_run[0] = l_run[0] * corr0 + s0;
            l_run[1] = l_run[1] * corr1 + s1;
            m_run[0] = mn0;
            m_run[1] = mn1;
#pragma unroll
            for (int nt = 0; nt < 16; nt++) {
                o[nt][0] *= corr0;
                o[nt][1] *= corr0;
                o[nt][2] *= corr1;
                o[nt][3] *= corr1;
            }
        }

        // ---- Write P (tf32) to smem ----
#pragma unroll
        for (int nt = 0; nt < 8; nt++) {
            *(float2*)&Ps[(16 * w + g) * PS_S + 8 * nt + 2 * t] =
                make_float2(f2tf32(sc[nt][0]), f2tf32(sc[nt][1]));
            *(float2*)&Ps[(16 * w + g + 8) * PS_S + 8 * nt + 2 * t] =
                make_float2(f2tf32(sc[nt][2]), f2tf32(sc[nt][3]));
        }
        __syncwarp();   // P rows of warp w are read only by warp w

        // ---- O += P @ V : 16 n-tiles x 8 k-steps ----
#pragma unroll
        for (int s = 0; s < 8; s++) {
            const int kc = 8 * s + t;
            uint32_t a0 = fbits(Ps[(16 * w + g) * PS_S + kc]);
            uint32_t a1 = fbits(Ps[(16 * w + g + 8) * PS_S + kc]);
            uint32_t a2 = fbits(Ps[(16 * w + g) * PS_S + kc + 4]);
            uint32_t a3 = fbits(Ps[(16 * w + g + 8) * PS_S + kc + 4]);
#pragma unroll
            for (int nt = 0; nt < 16; nt++) {
                uint32_t b0 = fbits(Vs[(8 * s + t) * VS_S + 8 * nt + g]);
                uint32_t b1 = fbits(Vs[(8 * s + t + 4) * VS_S + 8 * nt + g]);
                mma_tf32(o[nt], a0, a1, a2, a3, b0, b1);
            }
        }
        __syncthreads();   // all warps done reading Ks/Vs before next fill
    }

    // ---- Normalize and store ----
    const float inv0 = 1.0f / l_run[0];
    const float inv1 = 1.0f / l_run[1];
    float* obase = out + ((size_t)b * Ss + q0 + 16 * w + g) * Nn;
#pragma unroll
    for (int nt = 0; nt < 16; nt++) {
        *(float2*)&obase[8 * nt + 2 * t] =
            make_float2(o[nt][0] * inv0, o[nt][1] * inv0);
        *(float2*)&obase[8 * (size_t)Nn + 8 * nt + 2 * t] =
            make_float2(o[nt][2] * inv1, o[nt][3] * inv1);
    }
}

// ---------------------------------------------------------------------------
// Launch
// ---------------------------------------------------------------------------
extern "C" void kernel_launch(void* const* d_in, const int* in_sizes, int n_in,
                              void* d_out, int out_size)
{
    const float* x  = (const float*)d_in[0];
    const float* Wq = (const float*)d_in[1];
    const float* Wk = (const float*)d_in[2];
    const float* Wv = (const float*)d_in[3];
    float* out = (float*)d_out;

    (void)in_sizes; (void)n_in; (void)out_size;

    cudaFuncSetAttribute(attn_kernel,
                         cudaFuncAttributeMaxDynamicSharedMemorySize,
                         ATT_SMEM_BYTES);

    qkv_gemm_kernel<<<dim3(Ss * Bb / 128, 3), 256>>>(x, Wq, Wk, Wv);
    attn_kernel<<<dim3(Ss / 128, Bb), 256, ATT_SMEM_BYTES>>>(out);
}